// round 17
// baseline (speedup 1.0000x reference)
#include <cuda_runtime.h>
#include <cfloat>

#define NPTS 4096
#define MQ   1024
#define CCH  64
#define QPB  2            // queries per CTA (merged scan)
#define NB   (MQ / QPB)   // 512 CTAs x 512 threads = 8192 warps
#define NT   512
#define LCAP 512          // per-query candidate capacity (expect ~41)

__global__ __launch_bounds__(NT, 4)
void maxpool_fused_kernel(const float* __restrict__ values,
                          const float* __restrict__ coords,
                          const float* __restrict__ qcoords,
                          float* __restrict__ out) {
    __shared__ int   s_list[QPB][LCAP];
    __shared__ int   s_cnt[QPB];
    __shared__ float s_part[16][CCH];

    const int tid  = threadIdx.x;
    const int lane = tid & 31;
    const int w    = tid >> 5;          // warp 0..15

    if (tid < QPB) s_cnt[tid] = 0;

    // Both queries of this CTA in one LDG.128 (rows 2b and 2b+1 contiguous).
    const float4 qq = ((const float4*)qcoords)[blockIdx.x];
    const float q0x = qq.x, q0y = qq.y, q1x = qq.z, q1y = qq.w;

    __syncthreads();

    // ---- Phase 1: merged dual-query scan. Each thread: 4 x LDG.128
    // (8 points), each point tested against both queries. Branch-free masks.
    const float4* __restrict__ c4 = (const float4*)coords;
    float4 cc[4];
    #pragma unroll
    for (int it = 0; it < 4; it++) cc[it] = c4[it * NT + tid];

    unsigned m0 = 0, m1 = 0;
    #pragma unroll
    for (int it = 0; it < 4; it++) {
        float4 c = cc[it];
        bool a0 = fmaxf(fabsf(q0x - c.x), fabsf(q0y - c.y)) < 0.05f;
        bool a1 = fmaxf(fabsf(q0x - c.z), fabsf(q0y - c.w)) < 0.05f;
        bool b0 = fmaxf(fabsf(q1x - c.x), fabsf(q1y - c.y)) < 0.05f;
        bool b1 = fmaxf(fabsf(q1x - c.z), fabsf(q1y - c.w)) < 0.05f;
        m0 |= (a0 ? (1u << (2 * it)) : 0u);
        m0 |= (a1 ? (2u << (2 * it)) : 0u);
        m1 |= (b0 ? (1u << (2 * it)) : 0u);
        m1 |= (b1 ? (2u << (2 * it)) : 0u);
    }

    // ---- Warp-aggregated push: packed inclusive scan (both queries in one
    // 32-bit lane value), one shared atomic per warp per query, offset writes.
    const int c0 = __popc(m0), c1 = __popc(m1);
    unsigned pk = (unsigned)c0 | ((unsigned)c1 << 16);
    #pragma unroll
    for (int d = 1; d < 32; d <<= 1) {
        unsigned n = __shfl_up_sync(0xFFFFFFFFu, pk, d);
        if (lane >= d) pk += n;
    }
    unsigned tot = __shfl_sync(0xFFFFFFFFu, pk, 31);
    int b0 = 0, b1 = 0;
    if (lane == 31) {
        b0 = atomicAdd(&s_cnt[0], (int)(tot & 0xFFFFu));
        b1 = atomicAdd(&s_cnt[1], (int)(tot >> 16));
    }
    b0 = __shfl_sync(0xFFFFFFFFu, b0, 31);
    b1 = __shfl_sync(0xFFFFFFFFu, b1, 31);
    int off0 = b0 + (int)(pk & 0xFFFFu) - c0;   // exclusive prefix
    int off1 = b1 + (int)(pk >> 16) - c1;

    while (m0) {
        int b = __ffs(m0) - 1; m0 &= m0 - 1;
        if (off0 < LCAP) s_list[0][off0] = 2 * ((b >> 1) * NT + tid) + (b & 1);
        off0++;
    }
    while (m1) {
        int b = __ffs(m1) - 1; m1 &= m1 - 1;
        if (off1 < LCAP) s_list[1][off1] = 2 * ((b >> 1) * NT + tid) + (b & 1);
        off1++;
    }
    __syncthreads();

    // ---- Phase 2: gather-max. 8 warp-slices per query; lane owns channels
    // {2*lane, 2*lane+1} -> coalesced 256B float2 rows. Unroll-4 MLP.
    const int qs  = w >> 3;              // query slot 0/1
    const int wq  = w & 7;               // warp within query 0..7
    const int cnt = min(s_cnt[qs], LCAP);

    const float2* __restrict__ v2 = (const float2*)values;
    float r0 = -FLT_MAX, r1 = -FLT_MAX;

    int j = wq;
    for (; j + 32 <= cnt; j += 32) {
        int i0 = s_list[qs][j +  0];
        int i1 = s_list[qs][j +  8];
        int i2 = s_list[qs][j + 16];
        int i3 = s_list[qs][j + 24];
        float2 a = v2[i0 * 32 + lane];
        float2 b = v2[i1 * 32 + lane];
        float2 c = v2[i2 * 32 + lane];
        float2 d = v2[i3 * 32 + lane];
        r0 = fmaxf(r0, fmaxf(fmaxf(a.x, b.x), fmaxf(c.x, d.x)));
        r1 = fmaxf(r1, fmaxf(fmaxf(a.y, b.y), fmaxf(c.y, d.y)));
    }
    for (; j < cnt; j += 8) {
        float2 a = v2[s_list[qs][j] * 32 + lane];
        r0 = fmaxf(r0, a.x);
        r1 = fmaxf(r1, a.y);
    }

    s_part[w][2 * lane]     = r0;
    s_part[w][2 * lane + 1] = r1;
    __syncthreads();

    // ---- Final reduce: threads 0-127 cover both queries' 64 channels.
    if (tid < QPB * CCH) {
        const int qsel = tid >> 6;
        const int ch   = tid & (CCH - 1);
        float r = s_part[qsel * 8][ch];
        #pragma unroll
        for (int k = 1; k < 8; k++) r = fmaxf(r, s_part[qsel * 8 + k][ch]);
        out[(blockIdx.x * QPB + qsel) * CCH + ch] = r;
    }
}

extern "C" void kernel_launch(void* const* d_in, const int* in_sizes, int n_in,
                              void* d_out, int out_size) {
    const float* values  = (const float*)d_in[0];   // [N, C] f32
    const float* coords  = (const float*)d_in[1];   // [N, 2] f32
    const float* qcoords = (const float*)d_in[2];   // [M, 2] f32
    float* out = (float*)d_out;                     // [M, C] f32

    maxpool_fused_kernel<<<NB, NT>>>(values, coords, qcoords, out);
}